// round 13
// baseline (speedup 1.0000x reference)
#include <cuda_runtime.h>

// GCN_33560874451187 — scalarized 2-layer GCN, single-level col binning.
// N=500000, E=16000000 (int32 edges).
// Bucket = col>>12 (123 buckets, 4096-col window). rec = collocal<<19 | row.
// k_bin: ONE global read pass; rec+rank held in registers; tile-sorted smem
// shuffle; coalesced per-bucket copy-out.
// deg + both aggs consume bins with a 16KB smem window accumulator.

#define NN     500000
#define NE     16000000
#define CLB    12
#define CW     4096                 // col window size
#define NBK    123                  // ceil(NN/CW)
#define STRIDE 140000               // per-bucket capacity (mean ~131K)
#define TILE   8192
#define BT     512                  // bin threads (16 edges/thread)
#define CT     256                  // consumer threads
#define BPB    8                    // consumer blocks per bucket

__device__ unsigned g_bins[(size_t)NBK * STRIDE];  // ~69MB
__device__ unsigned g_tail[NBK];
__device__ int      g_deg[NN];
__device__ float    g_dinv[NN];
__device__ float    g_val[NN];
__device__ float    g_acc[NN];

// ---------------------------------------------------------------------------

__global__ void k_zero_deg(int lo, int hi) {
    int i = lo + blockIdx.x * blockDim.x + threadIdx.x;
    if (i < hi) g_deg[i] = 0;
}
__global__ void k_zero_tail() {
    int i = threadIdx.x;
    if (i < NBK) g_tail[i] = 0u;
}

// Tile-sorted binning, register-staged records.
__global__ void k_bin(const int* __restrict__ row, const int* __restrict__ col, int e) {
    __shared__ unsigned s_sorted[TILE];          // 32KB
    __shared__ unsigned s_cnt[128], s_lb[128], s_gb[128];

    int t = threadIdx.x;
    int tb = blockIdx.x * TILE;
    int nE = e - tb; if (nE > TILE) nE = TILE;

    if (t < 128) s_cnt[t] = 0u;
    __syncthreads();

    // single global read pass: rec + (rank,bucket) into registers
    unsigned rec[16], rb[16];
    #pragma unroll
    for (int i = 0; i < 16; i++) {
        int k = t + i * BT;
        if (k < nE) {
            int r = row[tb + k];
            int c = col[tb + k];
            unsigned b = (unsigned)c >> CLB;
            unsigned rank = atomicAdd(&s_cnt[b], 1u);
            rec[i] = ((unsigned)(c & (CW - 1)) << 19) | (unsigned)r;
            rb[i]  = (rank << 8) | b;            // rank<=8191 fits in 24 bits
        } else {
            rb[i] = 0xFFFFFFFFu;
        }
    }
    __syncthreads();

    // exclusive scan of 128 counters: warp shfl-scan + warp-total fixup
    if (t < 128) {
        unsigned lane = t & 31, w = t >> 5;
        unsigned v = s_cnt[t], p = v;
        #pragma unroll
        for (int o = 1; o < 32; o <<= 1) {
            unsigned u = __shfl_up_sync(0xFFFFFFFFu, p, o);
            if (lane >= o) p += u;
        }
        s_lb[t] = p - v;
        if (lane == 31) s_gb[w] = p;             // warp total (temp)
    }
    __syncthreads();
    if (t < 128) {
        unsigned w = t >> 5, off = 0;
        for (unsigned j = 0; j < w; j++) off += s_gb[j];
        s_lb[t] += off;
    }
    __syncthreads();
    if (t < 128) {
        unsigned c = s_cnt[t];
        s_gb[t] = c ? atomicAdd(&g_tail[t], c) : 0u;
    }
    __syncthreads();

    // smem shuffle into bucket-sorted order (registers -> smem)
    #pragma unroll
    for (int i = 0; i < 16; i++) {
        if (rb[i] != 0xFFFFFFFFu) {
            unsigned b = rb[i] & 255u, rank = rb[i] >> 8;
            s_sorted[s_lb[b] + rank] = rec[i];
        }
    }
    __syncthreads();

    // contiguous copy-out: warp per bucket (~268B runs)
    int w = t >> 5, lane = t & 31;
    for (int b = w; b < NBK; b += (BT / 32)) {
        unsigned cnt = s_cnt[b];
        if (!cnt) continue;
        unsigned gb = s_gb[b];
        if (gb + cnt > STRIDE) cnt = (gb < STRIDE) ? (STRIDE - gb) : 0u;  // never triggers
        unsigned* dst = g_bins + (size_t)b * STRIDE + gb;
        unsigned lb = s_lb[b];
        for (unsigned i = lane; i < cnt; i += 32) dst[i] = s_sorted[lb + i];
    }
}

// In-degree from bins: 16KB smem histogram per col window + merge REDs.
__global__ void k_degb(int n) {
    __shared__ unsigned s_cnt[CW];
    int t = threadIdx.x;
    int b = blockIdx.x / BPB, j = blockIdx.x % BPB;
    unsigned cnt = g_tail[b]; if (cnt > STRIDE) cnt = STRIDE;
    unsigned start = (unsigned)(((unsigned long long)cnt * j) / BPB);
    unsigned end   = (unsigned)(((unsigned long long)cnt * (j + 1)) / BPB);

    for (int i = t; i < CW; i += CT) s_cnt[i] = 0u;
    __syncthreads();

    const unsigned* recs = g_bins + (size_t)b * STRIDE;
    for (unsigned k = start + t; k < end; k += CT)
        atomicAdd(&s_cnt[recs[k] >> 19], 1u);
    __syncthreads();

    int base = b << CLB;
    for (int i = t; i < CW; i += CT) {
        unsigned c = s_cnt[i];
        if (c && base + i < n) atomicAdd(&g_deg[base + i], (int)c);
    }
}

// Aggregation from bins: gather val (L2) + smem window accumulate + merge.
__global__ void k_aggb(int n) {
    __shared__ float s_acc[CW];
    int t = threadIdx.x;
    int b = blockIdx.x / BPB, j = blockIdx.x % BPB;
    unsigned cnt = g_tail[b]; if (cnt > STRIDE) cnt = STRIDE;
    unsigned start = (unsigned)(((unsigned long long)cnt * j) / BPB);
    unsigned end   = (unsigned)(((unsigned long long)cnt * (j + 1)) / BPB);

    for (int i = t; i < CW; i += CT) s_acc[i] = 0.0f;
    __syncthreads();

    const unsigned* recs = g_bins + (size_t)b * STRIDE;
    for (unsigned k = start + t; k < end; k += CT) {
        unsigned rec = recs[k];
        atomicAdd(&s_acc[rec >> 19], __ldg(&g_val[rec & 0x7FFFFu]));
    }
    __syncthreads();

    int base = b << CLB;
    for (int i = t; i < CW; i += CT) {
        float v = s_acc[i];
        if (v != 0.0f && base + i < n) atomicAdd(&g_acc[base + i], v);
    }
}

// --- node-wise kernels -----------------------------------------------------

__global__ void k_phase1(const float* __restrict__ x, int n) {
    int i = blockIdx.x * blockDim.x + threadIdx.x;
    if (i < n) {
        float dinv = rsqrtf((float)(g_deg[i] + 1));
        g_dinv[i] = dinv;
        float y = dinv * x[i];
        g_val[i] = y;
        g_acc[i] = y;
    }
}

__global__ void k_phase2(const float* __restrict__ W1,
                         const float* __restrict__ b1,
                         const float* __restrict__ W2, int n) {
    int i = blockIdx.x * blockDim.x + threadIdx.x;
    if (i < n) {
        float dinv = g_dinv[i];
        float s1 = dinv * g_acc[i];
        float tacc = 0.0f;
        #pragma unroll
        for (int k = 0; k < 10; k++) {
            float h = fmaf(s1, __ldg(&W1[k]), __ldg(&b1[k]));
            tacc = fmaf(fmaxf(h, 0.0f), __ldg(&W2[k]), tacc);
        }
        float z = dinv * tacc;
        g_val[i] = z;
        g_acc[i] = z;
    }
}

__global__ void k_out(float* __restrict__ out, const float* __restrict__ b2, int n) {
    int i = blockIdx.x * blockDim.x + threadIdx.x;
    if (i < n) {
        float v = fmaf(g_dinv[i], g_acc[i], __ldg(&b2[0]));
        out[i] = fminf(fmaxf(v, -0.5f), 9.5f);
    }
}

// ---------------------------------------------------------------------------

extern "C" void kernel_launch(void* const* d_in, const int* in_sizes, int n_in,
                              void* d_out, int out_size) {
    const float* x   = (const float*)d_in[0];
    const int*   ei  = (const int*)d_in[1];
    const float* W1  = (const float*)d_in[2];
    const float* b1  = (const float*)d_in[3];
    const float* W2  = (const float*)d_in[4];
    const float* b2  = (const float*)d_in[5];
    float*       out = (float*)d_out;

    int n = in_sizes[0];
    int e = in_sizes[1] / 2;
    if (n > NN) n = NN;
    if (e > NE) e = NE;

    const int* row = ei;
    const int* col = ei + e;

    const int T = 256;
    int half  = n / 2;
    int nb_h1 = (half + T - 1) / T;
    int nb_h2 = (n - half + T - 1) / T;
    int nb_n  = (n + T - 1) / T;
    int nb_bin = (e + TILE - 1) / TILE;   // 1954
    int nb_con = NBK * BPB;               // 984

    // ncu captures launch index 3 -> k_bin this round
    k_zero_deg<<<nb_h1, T>>>(0, half);             // 0
    k_zero_deg<<<nb_h2, T>>>(half, n);             // 1
    k_zero_tail<<<1, 128>>>();                     // 2
    k_bin<<<nb_bin, BT>>>(row, col, e);            // 3  <- profiled
    k_degb<<<nb_con, CT>>>(n);                     // 4
    k_phase1<<<nb_n, T>>>(x, n);                   // 5
    k_aggb<<<nb_con, CT>>>(n);                     // 6
    k_phase2<<<nb_n, T>>>(W1, b1, W2, n);          // 7
    k_aggb<<<nb_con, CT>>>(n);                     // 8
    k_out<<<nb_n, T>>>(out, b2, n);                // 9
}

// round 14
// speedup vs baseline: 1.0191x; 1.0191x over previous
#include <cuda_runtime.h>

// GCN_33560874451187 — scalarized 2-layer GCN, col-window binning,
// consumer kernels with fused last-block node-phase tails.
// N=500000, E=16000000 (int32 edges).
// Bucket = col>>12 (123 buckets, 4096-col window). rec = collocal<<19 | row.
// Launches: zero, bin, deg(+phase1), agg1(+phase2), agg2(+out).

#define NN     500000
#define NE     16000000
#define CLB    12
#define CW     4096
#define NBK    123
#define STRIDE 140000
#define TILE   8192
#define BT     256                  // bin threads
#define CT     256                  // consumer threads
#define BPB    8                    // consumer blocks per bucket

__device__ unsigned g_bins[(size_t)NBK * STRIDE];  // ~69MB
__device__ unsigned g_tail[NBK];
__device__ unsigned g_arr1[NBK], g_arr2[NBK], g_arr3[NBK];
__device__ int      g_deg[NN];
__device__ float    g_dinv[NN];
__device__ float    g_val[NN];     // layer-1 y = dinv*x
__device__ float    g_val2[NN];    // layer-2 z
__device__ float    g_acc[NN];     // layer-1 accumulator
__device__ float    g_acc2[NN];    // layer-2 accumulator

// ---------------------------------------------------------------------------

__global__ void k_zero(int n) {
    int i = blockIdx.x * blockDim.x + threadIdx.x;
    if (i < NBK) { g_tail[i] = 0u; g_arr1[i] = 0u; g_arr2[i] = 0u; g_arr3[i] = 0u; }
    if (i < n) g_deg[i] = 0;
}

// Tile-sorted binning (R10 version: two read passes, u16 ranks).
__global__ void k_bin(const int* __restrict__ row, const int* __restrict__ col, int e) {
    __shared__ unsigned       s_sorted[TILE];   // 32KB
    __shared__ unsigned short s_rank[TILE];     // 16KB
    __shared__ unsigned s_cnt[128], s_lb[128], s_gb[128];

    int t = threadIdx.x;
    int tb = blockIdx.x * TILE;
    int nE = e - tb; if (nE > TILE) nE = TILE;

    if (t < 128) s_cnt[t] = 0u;
    __syncthreads();

    for (int k = t; k < nE; k += BT) {
        unsigned b = (unsigned)col[tb + k] >> CLB;
        s_rank[k] = (unsigned short)atomicAdd(&s_cnt[b], 1u);
    }
    __syncthreads();

    // exclusive scan of 128 counters
    if (t < 128) {
        unsigned lane = t & 31, w = t >> 5;
        unsigned v = s_cnt[t], p = v;
        #pragma unroll
        for (int o = 1; o < 32; o <<= 1) {
            unsigned u = __shfl_up_sync(0xFFFFFFFFu, p, o);
            if (lane >= o) p += u;
        }
        s_lb[t] = p - v;
        if (lane == 31) s_gb[w] = p;
    }
    __syncthreads();
    if (t < 128) {
        unsigned w = t >> 5, off = 0;
        for (unsigned j = 0; j < w; j++) off += s_gb[j];
        s_lb[t] += off;
    }
    __syncthreads();
    if (t < 128) {
        unsigned c = s_cnt[t];
        s_gb[t] = c ? atomicAdd(&g_tail[t], c) : 0u;
    }
    __syncthreads();

    for (int k = t; k < nE; k += BT) {
        int r = row[tb + k];                    // cold read
        int c = col[tb + k];                    // cache hit
        unsigned b = (unsigned)c >> CLB;
        unsigned rec = ((unsigned)(c & (CW - 1)) << 19) | (unsigned)r;
        s_sorted[s_lb[b] + (unsigned)s_rank[k]] = rec;
    }
    __syncthreads();

    // contiguous copy-out: warp per bucket
    int w = t >> 5, lane = t & 31;
    for (int b = w; b < NBK; b += (BT / 32)) {
        unsigned cnt = s_cnt[b];
        if (!cnt) continue;
        unsigned gb = s_gb[b];
        if (gb + cnt > STRIDE) cnt = (gb < STRIDE) ? (STRIDE - gb) : 0u;  // never triggers
        unsigned* dst = g_bins + (size_t)b * STRIDE + gb;
        unsigned lb = s_lb[b];
        for (unsigned i = lane; i < cnt; i += 32) dst[i] = s_sorted[lb + i];
    }
}

// helpers ------------------------------------------------------------------

__device__ __forceinline__ bool last_block(unsigned* arr, int b, int t,
                                           unsigned* s_last) {
    __threadfence();
    __syncthreads();
    if (t == 0) *s_last = atomicAdd(&arr[b], 1u);
    __syncthreads();
    if (*s_last == BPB - 1) { __threadfence(); return true; }
    return false;
}

// In-degree + fused phase1 tail.
__global__ void k_degp1(const float* __restrict__ x, int n) {
    __shared__ unsigned s_cnt[CW];
    __shared__ unsigned s_last;
    int t = threadIdx.x;
    int b = blockIdx.x / BPB, j = blockIdx.x % BPB;
    unsigned cnt = g_tail[b]; if (cnt > STRIDE) cnt = STRIDE;
    unsigned start = (unsigned)(((unsigned long long)cnt * j) / BPB);
    unsigned end   = (unsigned)(((unsigned long long)cnt * (j + 1)) / BPB);

    for (int i = t; i < CW; i += CT) s_cnt[i] = 0u;
    __syncthreads();

    const unsigned* recs = g_bins + (size_t)b * STRIDE;
    unsigned k = start + t;
    for (; k + 3u * CT < end; k += 4u * CT) {
        unsigned r0 = recs[k], r1 = recs[k + CT], r2 = recs[k + 2u * CT], r3 = recs[k + 3u * CT];
        atomicAdd(&s_cnt[r0 >> 19], 1u);
        atomicAdd(&s_cnt[r1 >> 19], 1u);
        atomicAdd(&s_cnt[r2 >> 19], 1u);
        atomicAdd(&s_cnt[r3 >> 19], 1u);
    }
    for (; k < end; k += CT) atomicAdd(&s_cnt[recs[k] >> 19], 1u);
    __syncthreads();

    int base = b << CLB;
    for (int i = t; i < CW; i += CT) {
        unsigned c = s_cnt[i];
        if (c && base + i < n) atomicAdd(&g_deg[base + i], (int)c);
    }

    if (last_block(g_arr1, b, t, &s_last)) {
        for (int i = t; i < CW; i += CT) {
            int idx = base + i;
            if (idx < n) {
                float dinv = rsqrtf((float)(g_deg[idx] + 1));
                g_dinv[idx] = dinv;
                float y = dinv * x[idx];
                g_val[idx] = y;
                g_acc[idx] = y;
            }
        }
    }
}

// Layer-1 aggregation + fused phase2 tail (writes g_val2/g_acc2 — no race
// with other buckets' in-flight g_val gathers).
__global__ void k_agg1(const float* __restrict__ W1,
                       const float* __restrict__ b1,
                       const float* __restrict__ W2, int n) {
    __shared__ float s_acc[CW];
    __shared__ unsigned s_last;
    int t = threadIdx.x;
    int b = blockIdx.x / BPB, j = blockIdx.x % BPB;
    unsigned cnt = g_tail[b]; if (cnt > STRIDE) cnt = STRIDE;
    unsigned start = (unsigned)(((unsigned long long)cnt * j) / BPB);
    unsigned end   = (unsigned)(((unsigned long long)cnt * (j + 1)) / BPB);

    for (int i = t; i < CW; i += CT) s_acc[i] = 0.0f;
    __syncthreads();

    const unsigned* recs = g_bins + (size_t)b * STRIDE;
    unsigned k = start + t;
    for (; k + 3u * CT < end; k += 4u * CT) {
        unsigned r0 = recs[k], r1 = recs[k + CT], r2 = recs[k + 2u * CT], r3 = recs[k + 3u * CT];
        float v0 = __ldg(&g_val[r0 & 0x7FFFFu]);
        float v1 = __ldg(&g_val[r1 & 0x7FFFFu]);
        float v2 = __ldg(&g_val[r2 & 0x7FFFFu]);
        float v3 = __ldg(&g_val[r3 & 0x7FFFFu]);
        atomicAdd(&s_acc[r0 >> 19], v0);
        atomicAdd(&s_acc[r1 >> 19], v1);
        atomicAdd(&s_acc[r2 >> 19], v2);
        atomicAdd(&s_acc[r3 >> 19], v3);
    }
    for (; k < end; k += CT) {
        unsigned rec = recs[k];
        atomicAdd(&s_acc[rec >> 19], __ldg(&g_val[rec & 0x7FFFFu]));
    }
    __syncthreads();

    int base = b << CLB;
    for (int i = t; i < CW; i += CT) {
        float v = s_acc[i];
        if (v != 0.0f && base + i < n) atomicAdd(&g_acc[base + i], v);
    }

    if (last_block(g_arr2, b, t, &s_last)) {
        for (int i = t; i < CW; i += CT) {
            int idx = base + i;
            if (idx < n) {
                float dinv = g_dinv[idx];
                float s1 = dinv * g_acc[idx];
                float tacc = 0.0f;
                #pragma unroll
                for (int q = 0; q < 10; q++) {
                    float h = fmaf(s1, __ldg(&W1[q]), __ldg(&b1[q]));
                    tacc = fmaf(fmaxf(h, 0.0f), __ldg(&W2[q]), tacc);
                }
                float z = dinv * tacc;
                g_val2[idx] = z;
                g_acc2[idx] = z;
            }
        }
    }
}

// Layer-2 aggregation + fused output tail.
__global__ void k_agg2(float* __restrict__ out, const float* __restrict__ b2, int n) {
    __shared__ float s_acc[CW];
    __shared__ unsigned s_last;
    int t = threadIdx.x;
    int b = blockIdx.x / BPB, j = blockIdx.x % BPB;
    unsigned cnt = g_tail[b]; if (cnt > STRIDE) cnt = STRIDE;
    unsigned start = (unsigned)(((unsigned long long)cnt * j) / BPB);
    unsigned end   = (unsigned)(((unsigned long long)cnt * (j + 1)) / BPB);

    for (int i = t; i < CW; i += CT) s_acc[i] = 0.0f;
    __syncthreads();

    const unsigned* recs = g_bins + (size_t)b * STRIDE;
    unsigned k = start + t;
    for (; k + 3u * CT < end; k += 4u * CT) {
        unsigned r0 = recs[k], r1 = recs[k + CT], r2 = recs[k + 2u * CT], r3 = recs[k + 3u * CT];
        float v0 = __ldg(&g_val2[r0 & 0x7FFFFu]);
        float v1 = __ldg(&g_val2[r1 & 0x7FFFFu]);
        float v2 = __ldg(&g_val2[r2 & 0x7FFFFu]);
        float v3 = __ldg(&g_val2[r3 & 0x7FFFFu]);
        atomicAdd(&s_acc[r0 >> 19], v0);
        atomicAdd(&s_acc[r1 >> 19], v1);
        atomicAdd(&s_acc[r2 >> 19], v2);
        atomicAdd(&s_acc[r3 >> 19], v3);
    }
    for (; k < end; k += CT) {
        unsigned rec = recs[k];
        atomicAdd(&s_acc[rec >> 19], __ldg(&g_val2[rec & 0x7FFFFu]));
    }
    __syncthreads();

    int base = b << CLB;
    for (int i = t; i < CW; i += CT) {
        float v = s_acc[i];
        if (v != 0.0f && base + i < n) atomicAdd(&g_acc2[base + i], v);
    }

    if (last_block(g_arr3, b, t, &s_last)) {
        for (int i = t; i < CW; i += CT) {
            int idx = base + i;
            if (idx < n) {
                float v = fmaf(g_dinv[idx], g_acc2[idx], __ldg(&b2[0]));
                out[idx] = fminf(fmaxf(v, -0.5f), 9.5f);
            }
        }
    }
}

// ---------------------------------------------------------------------------

extern "C" void kernel_launch(void* const* d_in, const int* in_sizes, int n_in,
                              void* d_out, int out_size) {
    const float* x   = (const float*)d_in[0];
    const int*   ei  = (const int*)d_in[1];
    const float* W1  = (const float*)d_in[2];
    const float* b1  = (const float*)d_in[3];
    const float* W2  = (const float*)d_in[4];
    const float* b2  = (const float*)d_in[5];
    float*       out = (float*)d_out;

    int n = in_sizes[0];
    int e = in_sizes[1] / 2;
    if (n > NN) n = NN;
    if (e > NE) e = NE;

    const int* row = ei;
    const int* col = ei + e;

    const int T = 256;
    int nb_n   = (n + T - 1) / T;
    int nb_bin = (e + TILE - 1) / TILE;   // 1954
    int nb_con = NBK * BPB;               // 984

    k_zero<<<nb_n, T>>>(n);                        // 0
    k_bin<<<nb_bin, BT>>>(row, col, e);            // 1
    k_degp1<<<nb_con, CT>>>(x, n);                 // 2
    k_agg1<<<nb_con, CT>>>(W1, b1, W2, n);         // 3  <- profiled
    k_agg2<<<nb_con, CT>>>(out, b2, n);            // 4
}